// round 17
// baseline (speedup 1.0000x reference)
#include <cuda_runtime.h>
#include <cuda_fp16.h>
#include <math.h>
#include <cstdint>

#define N_ATOMS 32768
#define MNBR    12
#define PROWS   16
#define ORIG    92
#define EDGE    41
#define FDIM    128
#define HDIM    256
#define NCONV   3
#define NCRY    128
#define APC     256
#define NT2     (N_ATOMS / 2)             // 16384 atom-pair tiles
#define ATILE   (N_ATOMS / 64)            // 512

// ---- scratch ----
__device__ float    g_x [N_ATOMS * FDIM];
__device__ uint32_t g_pc[N_ATOMS * 64];    // half2-packed phi_c
__device__ uint32_t g_yn[N_ATOMS * 64];    // half2-packed y_nbr
__device__ uint32_t g_nbrh[NT2 * 768];     // fp16 edge features, fragment order
__device__ float    g_site[N_ATOMS];

__device__ __forceinline__ uint32_t smem_u32(const void* p) {
    uint32_t a;
    asm("{ .reg .u64 t; cvta.to.shared.u64 t, %1; cvt.u32.u64 %0, t; }" : "=r"(a) : "l"(p));
    return a;
}
__device__ __forceinline__ uint32_t packh2(float a, float b) {
    __half2 h = __floats2half2_rn(a, b);
    return *(uint32_t*)&h;
}
__device__ __forceinline__ float2 unpackh2(uint32_t u) {
    return __half22float2(*(__half2*)&u);
}
__device__ __forceinline__ void mma_f16(float c[4], uint32_t a0, uint32_t a1,
                                        uint32_t a2, uint32_t a3,
                                        uint32_t b0, uint32_t b1) {
    asm volatile("mma.sync.aligned.m16n8k16.row.col.f32.f16.f16.f32 "
        "{%0,%1,%2,%3}, {%4,%5,%6,%7}, {%8,%9}, {%0,%1,%2,%3};"
        : "+f"(c[0]), "+f"(c[1]), "+f"(c[2]), "+f"(c[3])
        : "r"(a0), "r"(a1), "r"(a2), "r"(a3), "r"(b0), "r"(b1));
}
__device__ __forceinline__ float act(float g, float m) {
    float sig = __fdividef(1.f, 1.f + __expf(-g));
    float sp  = fmaxf(m, 0.f) + __logf(1.f + __expf(-fabsf(m)));
    return sig * sp;
}
__device__ __forceinline__ float spf(float x) {
    return fmaxf(x, 0.f) + __logf(1.f + __expf(-fabsf(x)));
}

extern __shared__ float sm[];

// ============================================================================
// Kernel 1: k_init — FUSED embed (blocks 0..147) + nbr_fea pack (blocks 148+)
//   embed: x = atom_fea @ W_embed + b   (fp16 mma GEMM, persistent)
//   pack:  nbr_fea -> fp16 fragment-order tiles in g_nbrh (grid-stride)
// ============================================================================
#define E_W    0
#define E_A    6144
#define E_BIAS 9472
#define E_TOT  9600
#define E_SMEM (E_TOT * 4)
#define EMB_BLOCKS  148
#define PACK_BLOCKS 296
#define INIT_GRID   (EMB_BLOCKS + PACK_BLOCKS)

__global__ void __launch_bounds__(256, 1)
k_init(const float* __restrict__ atom_fea,
       const float* __restrict__ W, const float* __restrict__ b,
       const float* __restrict__ nbr_fea) {
    int tid = threadIdx.x;

    if (blockIdx.x >= EMB_BLOCKS) {
        // ---------------- pack path ----------------
        int total = NT2 * 768;
        for (int idx = (blockIdx.x - EMB_BLOCKS) * 256 + tid; idx < total;
             idx += PACK_BLOCKS * 256) {
            int s = idx / 768, f = idx - s * 768;
            int c = f & 3, q = f >> 2;
            int lane = q & 31, rks = q >> 5;
            int rt = rks / 3, ks = rks - rt * 3;
            int tig = lane & 3, grp = lane >> 2;
            int slot = c >> 1, rowbit = c & 1;
            int m = grp + rowbit * 8;
            int k2 = ks * 8 + slot * 4 + tig;
            float v0 = 0.f, v1 = 0.f;
            if (m < MNBR) {
                size_t base = ((size_t)(s * 2 + rt) * MNBR + m) * EDGE;
                if (2 * k2     < EDGE) v0 = nbr_fea[base + 2 * k2];
                if (2 * k2 + 1 < EDGE) v1 = nbr_fea[base + 2 * k2 + 1];
            }
            g_nbrh[idx] = packh2(v0, v1);
        }
        return;
    }

    // ---------------- embed path ----------------
    int wid = tid >> 5, lane = tid & 31;
    uint32_t* smu = (uint32_t*)sm;
    for (int i = tid; i < 6144; i += 256) {
        int wc0 = i / 1536, rem = i - wc0 * 1536;
        int c = rem & 1, idx = rem >> 1;
        int ln = idx & 31, ksj = idx >> 5;
        int ks = ksj >> 2, j = ksj & 3;
        int tg = ln & 3, gp = ln >> 2;
        int n = wc0 * 32 + j * 8 + gp;
        int k2 = ks * 8 + c * 4 + tg;
        float v0 = (2 * k2     < ORIG) ? W[(2 * k2) * FDIM + n]     : 0.f;
        float v1 = (2 * k2 + 1 < ORIG) ? W[(2 * k2 + 1) * FDIM + n] : 0.f;
        smu[E_W + i] = packh2(v0, v1);
    }
    if (tid < FDIM) sm[E_BIAS + tid] = b[tid];
    __syncthreads();

    int wr = wid >> 2, wc = wid & 3;
    int tig = lane & 3, grp = lane >> 2;
    float br[4][2];
    #pragma unroll
    for (int j = 0; j < 4; j++) {
        int n0 = wc * 32 + j * 8 + 2 * tig;
        br[j][0] = sm[E_BIAS + n0]; br[j][1] = sm[E_BIAS + n0 + 1];
    }

    for (int t = blockIdx.x; t < ATILE; t += EMB_BLOCKS) {
        #pragma unroll
        for (int q = 0; q < 12; q++) {
            int i = tid + q * 256;
            int r = i / 48, k2 = i - r * 48;
            uint32_t v = 0u;
            if (k2 < 46) {
                float2 f2 = *(const float2*)&atom_fea[(size_t)(t * 64 + r) * ORIG + 2 * k2];
                v = packh2(f2.x, f2.y);
            }
            smu[E_A + r * 52 + k2] = v;
        }
        __syncthreads();

        float c[2][4][4] = {};
        #pragma unroll
        for (int ks = 0; ks < 6; ks++) {
            int k0 = ks * 8;
            uint32_t a[2][4];
            #pragma unroll
            for (int rt = 0; rt < 2; rt++) {
                int r = wr * 32 + rt * 16 + grp;
                a[rt][0] = smu[E_A + r * 52 + k0 + tig];
                a[rt][1] = smu[E_A + (r + 8) * 52 + k0 + tig];
                a[rt][2] = smu[E_A + r * 52 + k0 + 4 + tig];
                a[rt][3] = smu[E_A + (r + 8) * 52 + k0 + 4 + tig];
            }
            #pragma unroll
            for (int j = 0; j < 4; j++) {
                uint2 Bf = *(const uint2*)&smu[E_W + wc * 1536 + ((ks * 4 + j) * 32 + lane) * 2];
                #pragma unroll
                for (int rt = 0; rt < 2; rt++)
                    mma_f16(c[rt][j], a[rt][0], a[rt][1], a[rt][2], a[rt][3], Bf.x, Bf.y);
            }
        }

        #pragma unroll
        for (int rt = 0; rt < 2; rt++) {
            int r0 = t * 64 + wr * 32 + rt * 16 + grp;
            #pragma unroll
            for (int j = 0; j < 4; j++) {
                int n0 = wc * 32 + j * 8 + 2 * tig;
                *(float2*)&g_x[r0 * FDIM + n0] =
                    make_float2(c[rt][j][0] + br[j][0], c[rt][j][1] + br[j][1]);
                *(float2*)&g_x[(r0 + 8) * FDIM + n0] =
                    make_float2(c[rt][j][2] + br[j][0], c[rt][j][3] + br[j][1]);
            }
        }
        __syncthreads();
    }
}

// ============================================================================
// Kernel 2: k_convA — fp16 mma GEMM: [phi_c|y_nbr] = x @ [Wc|Wn] + bias
// ============================================================================
#define CA_W    0
#define CA_A    16384
#define CA_BIAS 20736
#define CA_TOT  20992
#define CA_SMEM (CA_TOT * 4)

__global__ void __launch_bounds__(256, 1)
k_convA(const float* __restrict__ Wc, const float* __restrict__ bc,
        const float* __restrict__ Wn, const float* __restrict__ bn) {
    int tid = threadIdx.x, wid = tid >> 5, lane = tid & 31;
    uint32_t* smu = (uint32_t*)sm;
    for (int i = tid; i < 16384; i += 256) {
        int wc0 = i >> 12, rem = i & 4095;
        int c = rem & 3, idx4 = rem >> 2;
        int ln = idx4 & 31, ksj = idx4 >> 5;
        int ks = ksj >> 2, j = ksj & 3;
        int tg = ln & 3, gp = ln >> 2;
        int n = wc0 * 32 + j * 8 + gp;
        int k2 = ks * 8 + (c & 1) * 4 + tg;
        const float* W = (c < 2) ? Wc : Wn;
        smu[CA_W + i] = packh2(W[(2 * k2) * FDIM + n], W[(2 * k2 + 1) * FDIM + n]);
    }
    if (tid < 128) { sm[CA_BIAS + tid] = bc[tid]; sm[CA_BIAS + 128 + tid] = bn[tid]; }
    __syncthreads();

    int wr = wid >> 2, wc = wid & 3;
    int tig = lane & 3, grp = lane >> 2;
    float bcr[4][2], bnr[4][2];
    #pragma unroll
    for (int j = 0; j < 4; j++) {
        int f0 = wc * 32 + j * 8 + 2 * tig;
        bcr[j][0] = sm[CA_BIAS + f0];       bcr[j][1] = sm[CA_BIAS + f0 + 1];
        bnr[j][0] = sm[CA_BIAS + 128 + f0]; bnr[j][1] = sm[CA_BIAS + 128 + f0 + 1];
    }

    for (int t = blockIdx.x; t < ATILE; t += gridDim.x) {
        #pragma unroll
        for (int q = 0; q < 16; q++) {
            int i = tid + q * 256;
            int r = i >> 6, k2 = i & 63;
            float2 f2 = *(const float2*)&g_x[(size_t)(t * 64 + r) * FDIM + 2 * k2];
            smu[CA_A + r * 68 + k2] = packh2(f2.x, f2.y);
        }
        __syncthreads();

        float cpc[2][4][4] = {}, cyn[2][4][4] = {};
        #pragma unroll
        for (int ks = 0; ks < 8; ks++) {
            int k0 = ks * 8;
            uint32_t a[2][4];
            #pragma unroll
            for (int rt = 0; rt < 2; rt++) {
                int r = wr * 32 + rt * 16 + grp;
                a[rt][0] = smu[CA_A + r * 68 + k0 + tig];
                a[rt][1] = smu[CA_A + (r + 8) * 68 + k0 + tig];
                a[rt][2] = smu[CA_A + r * 68 + k0 + 4 + tig];
                a[rt][3] = smu[CA_A + (r + 8) * 68 + k0 + 4 + tig];
            }
            #pragma unroll
            for (int j = 0; j < 4; j++) {
                uint4 Bf = *(const uint4*)&smu[CA_W + wc * 4096 + ((ks * 4 + j) * 32 + lane) * 4];
                #pragma unroll
                for (int rt = 0; rt < 2; rt++) {
                    mma_f16(cpc[rt][j], a[rt][0], a[rt][1], a[rt][2], a[rt][3], Bf.x, Bf.y);
                    mma_f16(cyn[rt][j], a[rt][0], a[rt][1], a[rt][2], a[rt][3], Bf.z, Bf.w);
                }
            }
        }

        #pragma unroll
        for (int rt = 0; rt < 2; rt++) {
            int r0 = t * 64 + wr * 32 + rt * 16 + grp;
            #pragma unroll
            for (int j = 0; j < 4; j++) {
                int h0 = wc * 16 + j * 4 + tig;
                g_pc[r0 * 64 + h0] =
                    packh2(cpc[rt][j][0] + bcr[j][0], cpc[rt][j][1] + bcr[j][1]);
                g_pc[(r0 + 8) * 64 + h0] =
                    packh2(cpc[rt][j][2] + bcr[j][0], cpc[rt][j][3] + bcr[j][1]);
                g_yn[r0 * 64 + h0] =
                    packh2(cyn[rt][j][0] + bnr[j][0], cyn[rt][j][1] + bnr[j][1]);
                g_yn[(r0 + 8) * 64 + h0] =
                    packh2(cyn[rt][j][2] + bnr[j][0], cyn[rt][j][3] + bnr[j][1]);
            }
        }
        __syncthreads();
    }
}

// ============================================================================
// Kernel 3: k_conv — fused conv layer (unchanged from round 16)
// ============================================================================
#define S_W     0
#define S_WE    16384
#define S_BIAS  19456
#define S_GRP   20096
#define GP_AGM  0
#define GP_AE   4096
#define GP_YN   6400
#define GP_RED  9936
#define GP_IDX  10448
#define GRPSZ   10544
#define S_TOT   (S_GRP + 2 * GRPSZ)
#define CV_SMEM (S_TOT * 4)
#define CV_THREADS 512

__device__ __forceinline__ void stage_ae_h(uint32_t dstbase, const char* __restrict__ src,
                                           int gtid) {
    if (gtid < 192) {
        asm volatile("cp.async.ca.shared.global [%0], [%1], 16;"
                     :: "r"(dstbase + (uint32_t)gtid * 16),
                        "l"(src + (size_t)gtid * 16) : "memory");
    }
}

__device__ __forceinline__ void stage_yn(uint32_t dstbase, const int* __restrict__ sx,
                                         int tn, int gtid) {
    #pragma unroll
    for (int q = 0; q < 2; q++) {
        int i = gtid + q * 256;
        if (i < 416) {
            int row = i >> 4, c = i & 15;
            const char* src = (row < 24)
                ? (const char*)(g_yn + (size_t)sx[row] * 64) + c * 16
                : (const char*)(g_pc + ((size_t)tn * 2 + (row - 24)) * 64) + c * 16;
            uint32_t d = dstbase + (uint32_t)(row * 68 + c * 4) * 4;
            asm volatile("cp.async.ca.shared.global [%0], [%1], 16;"
                         :: "r"(d), "l"(src) : "memory");
        }
    }
}

__global__ void __launch_bounds__(CV_THREADS, 1)
k_conv(const int* __restrict__ nbr_idx,
       const float* __restrict__ Wg, const float* __restrict__ bg,
       const float* __restrict__ Wm, const float* __restrict__ bm,
       const float* __restrict__ We, const float* __restrict__ be,
       const float* __restrict__ lns, const float* __restrict__ lnb) {
    int tid = threadIdx.x, wid = tid >> 5, lane = tid & 31;
    int half = wid >> 3, wg = wid & 7, gtid = tid & 255;
    uint32_t* smu = (uint32_t*)sm;

    for (int i = tid; i < 16384; i += CV_THREADS) {
        int wgo = i >> 11, rem = i & 2047;
        int c = rem & 3, idx4 = rem >> 2;
        int ln = idx4 & 31, ksj = idx4 >> 5;
        int ks = ksj >> 1, j = ksj & 1;
        int tg = ln & 3, gp = ln >> 2;
        int n = wgo * 16 + j * 8 + gp;
        int k2 = ks * 8 + (c & 1) * 4 + tg;
        const float* W = (c < 2) ? Wg : Wm;
        smu[S_W + i] = packh2(W[(2 * k2) * FDIM + n], W[(2 * k2 + 1) * FDIM + n]);
    }
    for (int i = tid; i < 3072; i += CV_THREADS) {
        int wgo = i / 384, rem = i - wgo * 384;
        int c = rem & 1, idx2 = rem >> 1;
        int ln = idx2 & 31, ksj = idx2 >> 5;
        int ks = ksj >> 1, j = ksj & 1;
        int tg = ln & 3, gp = ln >> 2;
        int n = wgo * 16 + j * 8 + gp;
        int k2 = ks * 8 + c * 4 + tg;
        float v0 = (2 * k2     < EDGE) ? We[(2 * k2) * FDIM + n]     : 0.f;
        float v1 = (2 * k2 + 1 < EDGE) ? We[(2 * k2 + 1) * FDIM + n] : 0.f;
        smu[S_WE + i] = packh2(v0, v1);
    }
    if (tid < FDIM) {
        sm[S_BIAS + tid]       = bg[tid];
        sm[S_BIAS + 128 + tid] = bm[tid];
        sm[S_BIAS + 256 + tid] = lns[tid];
        sm[S_BIAS + 384 + tid] = lnb[tid];
        sm[S_BIAS + 512 + tid] = be[tid];
    }

    int gbase = S_GRP + half * GRPSZ;
    int* sidx3 = (int*)(sm + gbase + GP_IDX);
    uint32_t aeRaw = smem_u32(sm + gbase + GP_AE);
    uint32_t ynRaw = smem_u32(sm + gbase + GP_YN);
    int tig = lane & 3, grp = lane >> 2;
    bool notpad = (grp < 4);
    int barid = half + 1;

    int stride = 2 * gridDim.x;
    int s0 = blockIdx.x * 2 + half;

    __syncthreads();

    if (gtid < 24) {
        sidx3[gtid] = nbr_idx[s0 * 24 + gtid];
        if (s0 + stride < NT2)
            sidx3[24 + gtid] = nbr_idx[(s0 + stride) * 24 + gtid];
    }
    stage_ae_h(aeRaw, (const char*)(g_nbrh + (size_t)s0 * 768), gtid);
    if (s0 + stride < NT2)
        stage_ae_h(aeRaw + 768u * 4, (const char*)(g_nbrh + (size_t)(s0 + stride) * 768), gtid);
    asm volatile("cp.async.commit_group;" ::: "memory");
    asm volatile("cp.async.wait_group 0;" ::: "memory");
    asm volatile("bar.sync %0, %1;" :: "r"(barid), "r"(256) : "memory");

    stage_yn(ynRaw, sidx3, s0, gtid);
    asm volatile("cp.async.commit_group;" ::: "memory");
    asm volatile("cp.async.wait_group 0;" ::: "memory");
    asm volatile("bar.sync %0, %1;" :: "r"(barid), "r"(256) : "memory");

    float bgr[2][2], bmr[2][2];
    #pragma unroll
    for (int j = 0; j < 2; j++) {
        int f0 = wg * 16 + j * 8 + 2 * tig;
        bgr[j][0] = sm[S_BIAS + f0];        bgr[j][1] = sm[S_BIAS + f0 + 1];
        bmr[j][0] = sm[S_BIAS + 128 + f0];  bmr[j][1] = sm[S_BIAS + 128 + f0 + 1];
    }

    int b2 = 0, b3 = 0, bA = 0, bR = 0;
    int tprev = -1;
    for (int t = s0; t < NT2; t += stride) {
        int aeB  = gbase + GP_AE + b3 * 768;
        int ynB  = gbase + GP_YN + b2 * 1768;
        int agmB = gbase + GP_AGM + bA * 2048;

        if (t + stride < NT2)
            stage_yn(ynRaw + (uint32_t)(b2 ^ 1) * 1768 * 4,
                     sidx3 + ((b3 + 1) % 3) * 24, t + stride, gtid);
        asm volatile("cp.async.commit_group;" ::: "memory");

        int t2 = t + 2 * stride;
        if (t2 < NT2) {
            int ib = (b3 + 2) % 3;
            if (gtid < 24) sidx3[ib * 24 + gtid] = nbr_idx[t2 * 24 + gtid];
            stage_ae_h(aeRaw + (uint32_t)ib * 768 * 4,
                       (const char*)(g_nbrh + (size_t)t2 * 768), gtid);
        }
        asm volatile("cp.async.commit_group;" ::: "memory");

        // ---- phi_e mma ----
        float ce[2][2][4] = {};
        #pragma unroll
        for (int ks = 0; ks < 3; ks++) {
            uint4 A[2];
            #pragma unroll
            for (int rt = 0; rt < 2; rt++)
                A[rt] = *(const uint4*)&smu[aeB + ((rt * 3 + ks) * 32 + lane) * 4];
            #pragma unroll
            for (int j = 0; j < 2; j++) {
                uint2 Bf = *(const uint2*)&smu[S_WE + wg * 384 + ((ks * 2 + j) * 32 + lane) * 2];
                #pragma unroll
                for (int rt = 0; rt < 2; rt++)
                    mma_f16(ce[rt][j], A[rt].x, A[rt].y, A[rt].z, A[rt].w, Bf.x, Bf.y);
            }
        }

        // ---- build inter tile into AGM[bA] ----
        #pragma unroll
        for (int rt = 0; rt < 2; rt++) {
            int yr0 = ynB + (rt * 12 + grp) * 68;
            int pr  = ynB + (24 + rt) * 68;
            #pragma unroll
            for (int j = 0; j < 2; j++) {
                int f0 = wg * 16 + j * 8 + 2 * tig;
                int h0 = wg * 8 + j * 4 + tig;
                float2 be2 = *(const float2*)&sm[S_BIAS + 512 + f0];
                float2 pc2 = unpackh2(smu[pr + h0]);
                float2 y0  = unpackh2(smu[yr0 + h0]);
                uint32_t lo = packh2(pc2.x * y0.x * (ce[rt][j][0] + be2.x),
                                     pc2.y * y0.y * (ce[rt][j][1] + be2.y));
                uint32_t hi = 0u;
                if (notpad) {
                    float2 y1 = unpackh2(smu[yr0 + 8 * 68 + h0]);
                    hi = packh2(pc2.x * y1.x * (ce[rt][j][2] + be2.x),
                                pc2.y * y1.y * (ce[rt][j][3] + be2.y));
                }
                *(uint2*)&smu[agmB + ((rt * 8 + wg) * 32 + lane) * 4 + j * 2] =
                    make_uint2(lo, hi);
            }
        }

        // ---- THE barrier ----
        asm volatile("cp.async.wait_group 1;" ::: "memory");
        asm volatile("bar.sync %0, %1;" :: "r"(barid), "r"(256) : "memory");

        // ---- gate/mag mma from AGM[bA] ----
        float cg[2][2][4] = {}, cmm[2][2][4] = {};
        #pragma unroll
        for (int ks = 0; ks < 8; ks++) {
            uint4 A[2];
            #pragma unroll
            for (int rt = 0; rt < 2; rt++)
                A[rt] = *(const uint4*)&smu[agmB + ((rt * 8 + ks) * 32 + lane) * 4];
            #pragma unroll
            for (int j = 0; j < 2; j++) {
                uint4 Bf = *(const uint4*)&smu[S_W + wg * 2048 + ((ks * 2 + j) * 32 + lane) * 4];
                #pragma unroll
                for (int rt = 0; rt < 2; rt++) {
                    mma_f16(cg[rt][j],  A[rt].x, A[rt].y, A[rt].z, A[rt].w, Bf.x, Bf.y);
                    mma_f16(cmm[rt][j], A[rt].x, A[rt].y, A[rt].z, A[rt].w, Bf.z, Bf.w);
                }
            }
        }

        // ---- deferred LayerNorm + residual for previous tile ----
        if (tprev >= 0 && wg < 2) {
            float4 v = *(const float4*)&sm[gbase + GP_RED + (bR ^ 1) * 256 + wg * 128 + lane * 4];
            float4 lns4 = *(const float4*)&sm[S_BIAS + 256 + lane * 4];
            float4 lnb4 = *(const float4*)&sm[S_BIAS + 384 + lane * 4];
            float s = v.x + v.y + v.z + v.w;
            float q = v.x*v.x + v.y*v.y + v.z*v.z + v.w*v.w;
            #pragma unroll
            for (int o = 16; o > 0; o >>= 1) {
                s += __shfl_xor_sync(0xffffffffu, s, o);
                q += __shfl_xor_sync(0xffffffffu, q, o);
            }
            float mu = s * (1.f / FDIM);
            float var = q * (1.f / FDIM) - mu * mu;
            float rstd = rsqrtf(var + 1e-6f);
            int n = tprev * 2 + wg;
            float4 x = *(float4*)&g_x[n * FDIM + lane * 4];
            x.x += (v.x - mu) * rstd * lns4.x + lnb4.x;
            x.y += (v.y - mu) * rstd * lns4.y + lnb4.y;
            x.z += (v.z - mu) * rstd * lns4.z + lnb4.z;
            x.w += (v.w - mu) * rstd * lns4.w + lnb4.w;
            *(float4*)&g_x[n * FDIM + lane * 4] = x;
        }

        // ---- activation + masked per-atom column sums into RED[bR] ----
        #pragma unroll
        for (int rt = 0; rt < 2; rt++) {
            #pragma unroll
            for (int j = 0; j < 2; j++) {
                float p0 = act(cg[rt][j][0] + bgr[j][0], cmm[rt][j][0] + bmr[j][0]);
                float p1 = act(cg[rt][j][1] + bgr[j][1], cmm[rt][j][1] + bmr[j][1]);
                if (notpad) {
                    p0 += act(cg[rt][j][2] + bgr[j][0], cmm[rt][j][2] + bmr[j][0]);
                    p1 += act(cg[rt][j][3] + bgr[j][1], cmm[rt][j][3] + bmr[j][1]);
                }
                #pragma unroll
                for (int o = 4; o < 32; o <<= 1) {
                    p0 += __shfl_xor_sync(0xffffffffu, p0, o);
                    p1 += __shfl_xor_sync(0xffffffffu, p1, o);
                }
                if (grp == 0) {
                    int f0 = wg * 16 + j * 8 + 2 * tig;
                    sm[gbase + GP_RED + bR * 256 + rt * 128 + f0]     = p0;
                    sm[gbase + GP_RED + bR * 256 + rt * 128 + f0 + 1] = p1;
                }
            }
        }

        tprev = t;
        bA ^= 1; bR ^= 1; b2 ^= 1; b3 = (b3 + 1) % 3;
    }

    // ---- epilogue: final LN for last tile ----
    asm volatile("bar.sync %0, %1;" :: "r"(barid), "r"(256) : "memory");
    if (tprev >= 0 && wg < 2) {
        float4 v = *(const float4*)&sm[gbase + GP_RED + (bR ^ 1) * 256 + wg * 128 + lane * 4];
        float4 lns4 = *(const float4*)&sm[S_BIAS + 256 + lane * 4];
        float4 lnb4 = *(const float4*)&sm[S_BIAS + 384 + lane * 4];
        float s = v.x + v.y + v.z + v.w;
        float q = v.x*v.x + v.y*v.y + v.z*v.z + v.w*v.w;
        #pragma unroll
        for (int o = 16; o > 0; o >>= 1) {
            s += __shfl_xor_sync(0xffffffffu, s, o);
            q += __shfl_xor_sync(0xffffffffu, q, o);
        }
        float mu = s * (1.f / FDIM);
        float var = q * (1.f / FDIM) - mu * mu;
        float rstd = rsqrtf(var + 1e-6f);
        int n = tprev * 2 + wg;
        float4 x = *(float4*)&g_x[n * FDIM + lane * 4];
        x.x += (v.x - mu) * rstd * lns4.x + lnb4.x;
        x.y += (v.y - mu) * rstd * lns4.y + lnb4.y;
        x.z += (v.z - mu) * rstd * lns4.z + lnb4.z;
        x.w += (v.w - mu) * rstd * lns4.w + lnb4.w;
        *(float4*)&g_x[n * FDIM + lane * 4] = x;
    }
}

// ============================================================================
// Kernel 4: k_readout — fp16 mma GEMM + fused softplus.Wout
// ============================================================================
#define R_W    0
#define R_A    16384
#define R_BH   20736
#define R_WO   20992
#define R_RED  21248
#define R_TOT  21504
#define R_SMEM (R_TOT * 4)

__global__ void __launch_bounds__(256, 1)
k_readout(const float* __restrict__ Wh, const float* __restrict__ bh,
          const float* __restrict__ Wout, const float* __restrict__ bout) {
    int tid = threadIdx.x, wid = tid >> 5, lane = tid & 31;
    uint32_t* smu = (uint32_t*)sm;
    for (int i = tid; i < 16384; i += 256) {
        int wc0 = i >> 12, rem = i & 4095;
        int c = rem & 1, idx = rem >> 1;
        int ln = idx & 31, ksj = idx >> 5;
        int ks = ksj >> 3, j = ksj & 7;
        int tg = ln & 3, gp = ln >> 2;
        int n = wc0 * 64 + j * 8 + gp;
        int k2 = ks * 8 + c * 4 + tg;
        smu[R_W + i] = packh2(Wh[(2 * k2) * HDIM + n], Wh[(2 * k2 + 1) * HDIM + n]);
    }
    sm[R_BH + tid] = bh[tid];
    sm[R_WO + tid] = Wout[tid];
    __syncthreads();

    int wr = wid >> 2, wc = wid & 3;
    int tig = lane & 3, grp = lane >> 2;
    float b0 = bout[0];
    float bhr[8][2], wor[8][2];
    #pragma unroll
    for (int j = 0; j < 8; j++) {
        int n0 = wc * 64 + j * 8 + 2 * tig;
        bhr[j][0] = sm[R_BH + n0]; bhr[j][1] = sm[R_BH + n0 + 1];
        wor[j][0] = sm[R_WO + n0]; wor[j][1] = sm[R_WO + n0 + 1];
    }

    for (int t = blockIdx.x; t < ATILE; t += gridDim.x) {
        #pragma unroll
        for (int q = 0; q < 16; q++) {
            int i = tid + q * 256;
            int r = i >> 6, k2 = i & 63;
            float2 f2 = *(const float2*)&g_x[(size_t)(t * 64 + r) * FDIM + 2 * k2];
            smu[R_A + r * 68 + k2] = packh2(f2.x, f2.y);
        }
        __syncthreads();

        float c[2][8][4] = {};
        #pragma unroll
        for (int ks = 0; ks < 8; ks++) {
            int k0 = ks * 8;
            uint32_t a[2][4];
            #pragma unroll
            for (int rt = 0; rt < 2; rt++) {
                int r = wr * 32 + rt * 16 + grp;
                a[rt][0] = smu[R_A + r * 68 + k0 + tig];
                a[rt][1] = smu[R_A + (r + 8) * 68 + k0 + tig];
                a[rt][2] = smu[R_A + r * 68 + k0 + 4 + tig];
                a[rt][3] = smu[R_A + (r + 8) * 68 + k0 + 4 + tig];
            }
            #pragma unroll
            for (int j = 0; j < 8; j++) {
                uint2 Bf = *(const uint2*)&smu[R_W + wc * 4096 + ((ks * 8 + j) * 32 + lane) * 2];
                #pragma unroll
                for (int rt = 0; rt < 2; rt++)
                    mma_f16(c[rt][j], a[rt][0], a[rt][1], a[rt][2], a[rt][3], Bf.x, Bf.y);
            }
        }

        #pragma unroll
        for (int rt = 0; rt < 2; rt++) {
            float p0 = 0.f, p1 = 0.f;
            #pragma unroll
            for (int j = 0; j < 8; j++) {
                p0 += spf(c[rt][j][0] + bhr[j][0]) * wor[j][0]
                    + spf(c[rt][j][1] + bhr[j][1]) * wor[j][1];
                p1 += spf(c[rt][j][2] + bhr[j][0]) * wor[j][0]
                    + spf(c[rt][j][3] + bhr[j][1]) * wor[j][1];
            }
            p0 += __shfl_xor_sync(0xffffffffu, p0, 1);
            p0 += __shfl_xor_sync(0xffffffffu, p0, 2);
            p1 += __shfl_xor_sync(0xffffffffu, p1, 1);
            p1 += __shfl_xor_sync(0xffffffffu, p1, 2);
            if (tig == 0) {
                int r = wr * 32 + rt * 16 + grp;
                sm[R_RED + r * 4 + wc]       = p0;
                sm[R_RED + (r + 8) * 4 + wc] = p1;
            }
        }
        __syncthreads();
        if (tid < 64) {
            float4 s4 = *(const float4*)&sm[R_RED + tid * 4];
            g_site[t * 64 + tid] = s4.x + s4.y + s4.z + s4.w + b0;
        }
        __syncthreads();
    }
}

// ============================================================================
// Kernel 5: per-crystal sum
// ============================================================================
__global__ void k_crystal(float* __restrict__ out) {
    __shared__ float red[8];
    int c = blockIdx.x, tid = threadIdx.x;
    float v = g_site[c * APC + tid];
    #pragma unroll
    for (int o = 16; o > 0; o >>= 1)
        v += __shfl_xor_sync(0xffffffffu, v, o);
    if ((tid & 31) == 0) red[tid >> 5] = v;
    __syncthreads();
    if (tid == 0) {
        float s = 0.f;
        #pragma unroll
        for (int i = 0; i < 8; i++) s += red[i];
        out[c] = s;
    }
}

// ============================================================================
extern "C" void kernel_launch(void* const* d_in, const int* in_sizes, int n_in,
                              void* d_out, int out_size) {
    const float* atom_fea = (const float*)d_in[0];
    const float* nbr_fea  = (const float*)d_in[1];
    const int*   nbr_idx  = (const int*)  d_in[2];
    const float* W_embed  = (const float*)d_in[3];
    const float* b_embed  = (const float*)d_in[4];
    const float* W_center = (const float*)d_in[5];
    const float* b_center = (const float*)d_in[6];
    const float* W_nbr    = (const float*)d_in[7];
    const float* b_nbr    = (const float*)d_in[8];
    const float* W_edge   = (const float*)d_in[9];
    const float* b_edge   = (const float*)d_in[10];
    const float* W_gate   = (const float*)d_in[11];
    const float* b_gate   = (const float*)d_in[12];
    const float* W_mag    = (const float*)d_in[13];
    const float* b_mag    = (const float*)d_in[14];
    const float* ln_scale = (const float*)d_in[15];
    const float* ln_bias  = (const float*)d_in[16];
    const float* W_h      = (const float*)d_in[17];
    const float* b_h      = (const float*)d_in[18];
    const float* W_out    = (const float*)d_in[19];
    const float* b_out    = (const float*)d_in[20];
    float* out = (float*)d_out;

    cudaFuncSetAttribute(k_init,    cudaFuncAttributeMaxDynamicSharedMemorySize, E_SMEM);
    cudaFuncSetAttribute(k_convA,   cudaFuncAttributeMaxDynamicSharedMemorySize, CA_SMEM);
    cudaFuncSetAttribute(k_conv,    cudaFuncAttributeMaxDynamicSharedMemorySize, CV_SMEM);
    cudaFuncSetAttribute(k_readout, cudaFuncAttributeMaxDynamicSharedMemorySize, R_SMEM);

    k_init<<<INIT_GRID, 256, E_SMEM>>>(atom_fea, W_embed, b_embed, nbr_fea);
    for (int l = 0; l < NCONV; l++) {
        k_convA<<<148, 256, CA_SMEM>>>(W_center + l * FDIM * FDIM, b_center + l * FDIM,
                                       W_nbr    + l * FDIM * FDIM, b_nbr    + l * FDIM);
        k_conv<<<148, CV_THREADS, CV_SMEM>>>(nbr_idx,
                                      W_gate + l * FDIM * FDIM, b_gate + l * FDIM,
                                      W_mag  + l * FDIM * FDIM, b_mag  + l * FDIM,
                                      W_edge + l * EDGE * FDIM, b_edge + l * FDIM,
                                      ln_scale + l * FDIM, ln_bias + l * FDIM);
    }
    k_readout<<<148, 256, R_SMEM>>>(W_h, b_h, W_out, b_out);
    k_crystal<<<NCRY, 256>>>(out);
}